// round 2
// baseline (speedup 1.0000x reference)
#include <cuda_runtime.h>

// Scalar scratch for the global max|x| reduction (uint bits of a nonnegative
// float are order-preserving, so atomicMax on uint works).
__device__ unsigned int g_max_bits;

__global__ void hx_init_kernel() { g_max_bits = 0u; }

__global__ void hx_maxabs_kernel(const float4* __restrict__ x, int n4) {
    float m = 0.0f;
    int stride = gridDim.x * blockDim.x;
    for (int i = blockIdx.x * blockDim.x + threadIdx.x; i < n4; i += stride) {
        float4 v = x[i];
        m = fmaxf(m, fmaxf(fmaxf(fabsf(v.x), fabsf(v.y)),
                           fmaxf(fabsf(v.z), fabsf(v.w))));
    }
#pragma unroll
    for (int o = 16; o > 0; o >>= 1)
        m = fmaxf(m, __shfl_xor_sync(0xffffffffu, m, o));
    __shared__ float warpmax[8];
    int lane = threadIdx.x & 31, wid = threadIdx.x >> 5;
    if (lane == 0) warpmax[wid] = m;
    __syncthreads();
    if (threadIdx.x == 0) {
        float bm = warpmax[0];
        int nw = blockDim.x >> 5;
        for (int w = 1; w < nw; ++w) bm = fmaxf(bm, warpmax[w]);
        atomicMax(&g_max_bits, __float_as_uint(bm));
    }
}

// Accurate tanh that is robust to --use_fast_math substitution:
// exp2f maps to MUFU.EX2 (<=2 ulp either way), __fdiv_rn is always IEEE.
// tanh(x) = (e - 1)/(e + 1), e = exp2(2*x*log2(e)).  Max abs error ~1-2 ulp
// (argument-rounding error is damped by the (1 - t^2) factor).
__device__ __forceinline__ float hx_tanh(float x) {
    float ax = fminf(fabsf(x), 30.0f);              // avoid exp2 overflow
    float e  = exp2f(ax * 2.8853900817779268f);     // 2*log2(e)
    float t  = __fdiv_rn(e - 1.0f, e + 1.0f);
    return copysignf(t, x);
}

// Each block: 32 segments of 72 contiguous floats (8 channels x 9 hw
// positions) = 2304 floats. Each of 288 threads owns one (segment, hw)
// group of 8 stride-9 cells: disjoint read/modify/write, in-place in SMEM.
__global__ __launch_bounds__(288) void hx_quant_kernel(
    const float* __restrict__ x, float* __restrict__ out,
    const int* __restrict__ bits_ptr) {
    __shared__ __align__(16) float tile[2304];
    const int tid = threadIdx.x;
    const long long blk = (long long)blockIdx.x * 2304;
    const float4* in4 = (const float4*)(x + blk);
    float4* out4 = (float4*)(out + blk);
    float4* t4 = (float4*)tile;

    // Coalesced 16B loads: 576 float4 per block, 2 per thread.
    t4[tid]        = in4[tid];
    t4[tid + 288]  = in4[tid + 288];
    __syncthreads();

    const float delta = (float)((1 << (bits_ptr[0] - 1)) - 1);   // 127 for bits=8
    const float M = hx_tanh(__uint_as_float(g_max_bits));        // max|tanh(x)|

    const int seg = tid / 9;           // 0..31
    const int hw  = tid - seg * 9;     // 0..8
    const int base = seg * 72 + hw;

    float v[8];
    int key[8];
#pragma unroll
    for (int k = 0; k < 8; ++k) {
        float t  = hx_tanh(tile[base + 9 * k]);
        float y  = __fdiv_rn(t, M);        // matches reference: y = t / max|t|
        float z  = y * delta;
        float vv = rintf(z);               // round-half-even == jnp.round
        v[k] = vv;
        // Tie-break key: larger |v| wins; among equal |v|, LOWER group index
        // wins (jax.lax.top_k stability) -> encode (7 - k) in low bits.
        key[k] = (((int)fabsf(vv)) << 3) | (7 - k);
    }
#pragma unroll
    for (int i = 0; i < 8; ++i) {
        int rank = 0;
#pragma unroll
        for (int j = 0; j < 8; ++j) rank += (key[j] > key[i]);
        float o = (rank < 4) ? __fdiv_rn(v[i], delta) : 0.0f;  // keep top-4
        tile[base + 9 * i] = o;            // in-place, cells owned by this thread
    }
    __syncthreads();

    // Coalesced 16B stores.
    out4[tid]       = t4[tid];
    out4[tid + 288] = t4[tid + 288];
}

extern "C" void kernel_launch(void* const* d_in, const int* in_sizes, int n_in,
                              void* d_out, int out_size) {
    const float* x = (const float*)d_in[0];
    const int* bits = (const int*)d_in[1];
    float* out = (float*)d_out;

    const int n = in_sizes[0];           // 2048*2048*3*3 = 37748736
    const int n4 = n >> 2;               // divisible by 4
    const int qblocks = n / 2304;        // 16384, exact (n = 16384*2304)

    hx_init_kernel<<<1, 1>>>();
    hx_maxabs_kernel<<<2048, 256>>>((const float4*)x, n4);
    hx_quant_kernel<<<qblocks, 288>>>(x, out, bits);
}

// round 3
// speedup vs baseline: 1.4216x; 1.4216x over previous
#include <cuda_runtime.h>

#define MAXABS_BLOCKS 2048

// Scratch: per-block maxima (written unconditionally -> no init needed),
// plus the final scalar (written unconditionally by the reduce kernel).
__device__ unsigned int g_partial[MAXABS_BLOCKS];
__device__ unsigned int g_max_bits;

// ---------------------------------------------------------------------------
// Pass 1: per-block max|x|. REVERSE traversal so the FRONT of x is read last
// and stays resident in L2 for the quant kernel's forward read.
// ---------------------------------------------------------------------------
__global__ __launch_bounds__(256) void hx_maxabs_kernel(
    const float4* __restrict__ x, int n4) {
    float m = 0.0f;
    const int stride = gridDim.x * blockDim.x;
    for (int i = blockIdx.x * blockDim.x + threadIdx.x; i < n4; i += stride) {
        float4 v = x[n4 - 1 - i];                       // reverse order
        m = fmaxf(m, fmaxf(fmaxf(fabsf(v.x), fabsf(v.y)),
                           fmaxf(fabsf(v.z), fabsf(v.w))));
    }
#pragma unroll
    for (int o = 16; o > 0; o >>= 1)
        m = fmaxf(m, __shfl_xor_sync(0xffffffffu, m, o));
    __shared__ float warpmax[8];
    const int lane = threadIdx.x & 31, wid = threadIdx.x >> 5;
    if (lane == 0) warpmax[wid] = m;
    __syncthreads();
    if (threadIdx.x == 0) {
        float bm = warpmax[0];
#pragma unroll
        for (int w = 1; w < 8; ++w) bm = fmaxf(bm, warpmax[w]);
        g_partial[blockIdx.x] = __float_as_uint(bm);    // plain store
    }
}

// ---------------------------------------------------------------------------
// Pass 1b: reduce 2048 partials -> g_max_bits (single block, plain store).
// ---------------------------------------------------------------------------
__global__ __launch_bounds__(256) void hx_reduce_kernel() {
    float m = 0.0f;
#pragma unroll
    for (int k = 0; k < MAXABS_BLOCKS / 256; ++k)
        m = fmaxf(m, __uint_as_float(g_partial[threadIdx.x + 256 * k]));
#pragma unroll
    for (int o = 16; o > 0; o >>= 1)
        m = fmaxf(m, __shfl_xor_sync(0xffffffffu, m, o));
    __shared__ float warpmax[8];
    const int lane = threadIdx.x & 31, wid = threadIdx.x >> 5;
    if (lane == 0) warpmax[wid] = m;
    __syncthreads();
    if (threadIdx.x == 0) {
        float bm = warpmax[0];
#pragma unroll
        for (int w = 1; w < 8; ++w) bm = fmaxf(bm, warpmax[w]);
        g_max_bits = __float_as_uint(bm);
    }
}

// Fast tanh: exp2 (MUFU.EX2) + __fdividef (MUFU.RCP + mul), ~2 ulp.
// Clamp keeps e+1 < 2^87 (well inside __fdividef's valid divisor range).
__device__ __forceinline__ float hx_tanh(float x) {
    float ax = fminf(fabsf(x), 30.0f);
    float e  = exp2f(ax * 2.8853900817779268f);     // exp(2*ax)
    float t  = __fdividef(e - 1.0f, e + 1.0f);
    return copysignf(t, x);
}

// ---------------------------------------------------------------------------
// Pass 2: quantize + per-group (8 channels, stride 9) top-4 keep.
// Each block stages 2304 contiguous floats (32 segments of 72 = 8ch x 9hw)
// in SMEM; each of 288 threads owns one group of 8 stride-9 cells.
// ---------------------------------------------------------------------------
__global__ __launch_bounds__(288) void hx_quant_kernel(
    const float* __restrict__ x, float* __restrict__ out,
    const int* __restrict__ bits_ptr) {
    __shared__ __align__(16) float tile[2304];
    const int tid = threadIdx.x;
    const long long blk = (long long)blockIdx.x * 2304;
    const float4* in4 = (const float4*)(x + blk);
    float4* out4 = (float4*)(out + blk);
    float4* t4 = (float4*)tile;

    // Coalesced 16B loads (576 float4 per block).
    t4[tid]       = in4[tid];
    t4[tid + 288] = in4[tid + 288];
    __syncthreads();

    const float delta     = (float)((1 << (bits_ptr[0] - 1)) - 1);  // 127
    const float M         = hx_tanh(__uint_as_float(g_max_bits));   // max|tanh(x)|
    const float s         = __fdiv_rn(delta, M);    // once per thread
    const float inv_delta = __fdiv_rn(1.0f, delta); // once per thread

    const int seg  = tid / 9;          // 0..31
    const int hw   = tid - seg * 9;    // 0..8
    const int base = seg * 72 + hw;

    int iv[8];
    int key[8];
    int rank[8];
#pragma unroll
    for (int k = 0; k < 8; ++k) {
        float t = hx_tanh(tile[base + 9 * k]);
        int v   = __float2int_rn(t * s);            // F2I.ROUND = half-even
        iv[k]   = v;
        // larger |v| wins; equal |v| -> lower channel index wins (top_k stable)
        key[k]  = (abs(v) << 3) | (7 - k);
        rank[k] = 0;
    }
    // Pairwise ranking: keys are distinct, rank[i] = #{j : key[j] > key[i]}.
#pragma unroll
    for (int i = 0; i < 8; ++i)
#pragma unroll
        for (int j = i + 1; j < 8; ++j) {
            if (key[i] > key[j]) rank[j]++; else rank[i]++;
        }
#pragma unroll
    for (int i = 0; i < 8; ++i) {
        float o = (rank[i] < 4) ? (float)iv[i] * inv_delta : 0.0f;
        tile[base + 9 * i] = o;        // cells owned exclusively by this thread
    }
    __syncthreads();

    // Coalesced streaming stores (out is never re-read; keep x in L2).
    __stcs(&out4[tid],       t4[tid]);
    __stcs(&out4[tid + 288], t4[tid + 288]);
}

extern "C" void kernel_launch(void* const* d_in, const int* in_sizes, int n_in,
                              void* d_out, int out_size) {
    const float* x  = (const float*)d_in[0];
    const int* bits = (const int*)d_in[1];
    float* out      = (float*)d_out;

    const int n  = in_sizes[0];          // 37748736
    const int n4 = n >> 2;
    const int qblocks = n / 2304;        // 16384 (exact)

    hx_maxabs_kernel<<<MAXABS_BLOCKS, 256>>>((const float4*)x, n4);
    hx_reduce_kernel<<<1, 256>>>();
    hx_quant_kernel<<<qblocks, 288>>>(x, out, bits);
}